// round 1
// baseline (speedup 1.0000x reference)
#include <cuda_runtime.h>

#define B 8
#define C 128
#define HW 65536
#define K 64
#define NTOT 524288.0f
#define BN_EPS 1e-5f

// ---------------- scratch (device globals; no allocation allowed) ----------------
__device__ float g_xw[(size_t)B * C * HW];      // 268 MB scratch for xw
__device__ float g_sums_x[B * K * C];           // segment sums of x
__device__ float g_cnt[B * K];                  // segment counts
__device__ float g_sumsq[C];                    // per-channel sum of xw^2
__device__ float g_means[B * K * C];
__device__ float g_M[C * C];                    // W @ W^T
__device__ float g_Y[B * K * C];                // means @ M
__device__ float g_adj[B * K * K];
__device__ float g_adjm[B * K * C];             // adj_nd @ means
__device__ float g_bias[B * C * K];             // [b][d][k] = s*adjm + t
__device__ float g_s[C];
__device__ float g_t[C];

// ---------------- f32x2 helpers ----------------
#define FMA2(d_, a_, b_) asm("fma.rn.f32x2 %0, %1, %2, %0;" : "+l"(d_) : "l"(a_), "l"(b_))
#define PACKF2(d_, f_)   asm("mov.b64 %0, {%1, %1};" : "=l"(d_) : "r"(__float_as_uint(f_)))

__device__ __forceinline__ float2 u2f(unsigned long long u) {
    float2 f;
    asm("mov.b64 {%0, %1}, %2;" : "=f"(f.x), "=f"(f.y) : "l"(u));
    return f;
}

// ---------------- kernel 0: zero accumulators ----------------
__global__ void k_zero() {
    int i = blockIdx.x * blockDim.x + threadIdx.x;
    if (i < B * K * C) g_sums_x[i] = 0.f;
    if (i < B * K)     g_cnt[i] = 0.f;
    if (i < C)         g_sumsq[i] = 0.f;
}

// ---------------- kernel 1: segment sums of x + counts ----------------
// grid: B*32 blocks, each handles 2048 pixels of one batch; 256 threads
__global__ __launch_bounds__(256) void k_segsum(const float* __restrict__ x,
                                                const int* __restrict__ idx) {
    __shared__ float ssum[C][K];     // [c][k]  (bank-friendly: inner index k)
    __shared__ int   sidx[2048];
    __shared__ float scnt[K];
    int b = blockIdx.x >> 5;
    int p0 = (blockIdx.x & 31) << 11;
    int tid = threadIdx.x;

    for (int i = tid; i < C * K; i += 256) ((float*)ssum)[i] = 0.f;
    if (tid < K) scnt[tid] = 0.f;
    __syncthreads();

    for (int i = tid; i < 2048; i += 256) {
        int k = idx[b * HW + p0 + i];
        sidx[i] = k;
        atomicAdd(&scnt[k], 1.f);
    }
    __syncthreads();

    const float* xb = x + (size_t)b * C * HW + p0;
    for (int c = 0; c < C; c++) {
        const float* xc = xb + (size_t)c * HW;
        for (int i = tid; i < 2048; i += 256) {
            atomicAdd(&ssum[c][sidx[i]], xc[i]);
        }
    }
    __syncthreads();

    for (int i = tid; i < C * K; i += 256) {
        int c = i >> 6, k = i & 63;
        atomicAdd(&g_sums_x[(b * K + k) * C + c], ssum[c][k]);
    }
    if (tid < K) atomicAdd(&g_cnt[b * K + tid], scnt[tid]);
}

// ---------------- kernel 2: GEMM xw = x @ weight (+ sum of xw^2 per channel) ----------------
// 128x128 tile per block (all 128 outputs x 128 pixels), K=128, f32x2 packed math.
// grid: 4096 blocks (8 batch * 512 pixel tiles), 256 threads.
__global__ __launch_bounds__(256, 2) void k_gemm(const float* __restrict__ x,
                                                 const float* __restrict__ w) {
    __shared__ __align__(16) float Ws[2][16][128];
    __shared__ __align__(16) float Xs[2][16][132];
    __shared__ float sq[128];

    int b = blockIdx.x >> 9;
    int p0 = (blockIdx.x & 511) << 7;
    int tid = threadIdx.x;
    int tx = tid & 15, ty = tid >> 4;
    int lrow = tid >> 5;             // 0..7
    int lcol = (tid & 31) << 2;      // 0..124
    const float* xb = x + (size_t)b * C * HW + p0;

    if (tid < 128) sq[tid] = 0.f;

    unsigned long long acc[8][4];    // [d][p-pair]
#pragma unroll
    for (int i = 0; i < 8; i++)
#pragma unroll
        for (int j = 0; j < 4; j++) acc[i][j] = 0ULL;

    // prefetch chunk 0
    float4 wr0 = *(const float4*)(w + (size_t)lrow * C + lcol);
    float4 wr1 = *(const float4*)(w + (size_t)(lrow + 8) * C + lcol);
    float4 xr0 = *(const float4*)(xb + (size_t)lrow * HW + lcol);
    float4 xr1 = *(const float4*)(xb + (size_t)(lrow + 8) * HW + lcol);
    *(float4*)&Ws[0][lrow][lcol] = wr0;
    *(float4*)&Ws[0][lrow + 8][lcol] = wr1;
    *(float4*)&Xs[0][lrow][lcol] = xr0;
    *(float4*)&Xs[0][lrow + 8][lcol] = xr1;
    __syncthreads();

    for (int c0 = 0; c0 < C; c0 += 16) {
        int buf = (c0 >> 4) & 1;
        bool more = (c0 + 16) < C;
        if (more) {
            wr0 = *(const float4*)(w + (size_t)(c0 + 16 + lrow) * C + lcol);
            wr1 = *(const float4*)(w + (size_t)(c0 + 24 + lrow) * C + lcol);
            xr0 = *(const float4*)(xb + (size_t)(c0 + 16 + lrow) * HW + lcol);
            xr1 = *(const float4*)(xb + (size_t)(c0 + 24 + lrow) * HW + lcol);
        }
#pragma unroll
        for (int kk = 0; kk < 16; kk++) {
            float4 a0 = *(const float4*)&Ws[buf][kk][ty * 8];
            float4 a1 = *(const float4*)&Ws[buf][kk][ty * 8 + 4];
            ulonglong2 b0 = *(const ulonglong2*)&Xs[buf][kk][tx * 8];
            ulonglong2 b1 = *(const ulonglong2*)&Xs[buf][kk][tx * 8 + 4];
            unsigned long long bv[4];
            bv[0] = b0.x; bv[1] = b0.y; bv[2] = b1.x; bv[3] = b1.y;
            unsigned long long a2[8];
            PACKF2(a2[0], a0.x); PACKF2(a2[1], a0.y);
            PACKF2(a2[2], a0.z); PACKF2(a2[3], a0.w);
            PACKF2(a2[4], a1.x); PACKF2(a2[5], a1.y);
            PACKF2(a2[6], a1.z); PACKF2(a2[7], a1.w);
#pragma unroll
            for (int i = 0; i < 8; i++)
#pragma unroll
                for (int j = 0; j < 4; j++) FMA2(acc[i][j], a2[i], bv[j]);
        }
        __syncthreads();
        if (more) {
            *(float4*)&Ws[buf ^ 1][lrow][lcol] = wr0;
            *(float4*)&Ws[buf ^ 1][lrow + 8][lcol] = wr1;
            *(float4*)&Xs[buf ^ 1][lrow][lcol] = xr0;
            *(float4*)&Xs[buf ^ 1][lrow + 8][lcol] = xr1;
            __syncthreads();
        }
    }

    // epilogue: write xw tile, accumulate per-channel sum of squares
    float* xwr = g_xw + (size_t)b * C * HW + p0;
#pragma unroll
    for (int i = 0; i < 8; i++) {
        int d = ty * 8 + i;
        float2 f0 = u2f(acc[i][0]);
        float2 f1 = u2f(acc[i][1]);
        float2 f2 = u2f(acc[i][2]);
        float2 f3 = u2f(acc[i][3]);
        float4 v0 = make_float4(f0.x, f0.y, f1.x, f1.y);
        float4 v1 = make_float4(f2.x, f2.y, f3.x, f3.y);
        *(float4*)(xwr + (size_t)d * HW + tx * 8) = v0;
        *(float4*)(xwr + (size_t)d * HW + tx * 8 + 4) = v1;
        float s = v0.x * v0.x + v0.y * v0.y + v0.z * v0.z + v0.w * v0.w +
                  v1.x * v1.x + v1.y * v1.y + v1.z * v1.z + v1.w * v1.w;
        atomicAdd(&sq[d], s);
    }
    __syncthreads();
    if (tid < 128) atomicAdd(&g_sumsq[tid], sq[tid]);
}

// ---------------- kernel 3: means[b,k,d] = (sums_x[b,k,:] @ weight) / denom ----------------
// grid: B*K blocks, 128 threads (thread = d)
__global__ void k_means(const float* __restrict__ w) {
    __shared__ float s[C];
    int bk = blockIdx.x;
    int d = threadIdx.x;
    s[d] = g_sums_x[bk * C + d];
    __syncthreads();
    float cnt = g_cnt[bk];
    float denom = (cnt == 0.f) ? 1.f : cnt;
    float acc = 0.f;
#pragma unroll 8
    for (int c = 0; c < C; c++) acc += s[c] * w[c * C + d];
    g_means[bk * C + d] = acc / denom;
}

// ---------------- kernel 4: M = W @ W^T ----------------
// grid: 128 blocks (row i), 128 threads (col j)
__global__ void k_M(const float* __restrict__ Wm) {
    __shared__ float wi[C];
    int i = blockIdx.x, j = threadIdx.x;
    wi[j] = Wm[i * C + j];
    __syncthreads();
    float acc = 0.f;
#pragma unroll 8
    for (int c = 0; c < C; c++) acc += wi[c] * Wm[j * C + c];
    g_M[i * C + j] = acc;
}

// ---------------- kernel 5: Y[b,k,d] = means[b,k,:] @ M ----------------
__global__ void k_Y() {
    __shared__ float ms[C];
    int bk = blockIdx.x;
    int d = threadIdx.x;
    ms[d] = g_means[bk * C + d];
    __syncthreads();
    float acc = 0.f;
#pragma unroll 8
    for (int c = 0; c < C; c++) acc += ms[c] * g_M[c * C + d];
    g_Y[bk * C + d] = acc;
}

// ---------------- kernel 6: adjacency + adj_means ----------------
// grid: B blocks, 256 threads
__global__ __launch_bounds__(256) void k_adj(const float* __restrict__ adj_mask) {
    __shared__ float msm[K][C + 1];
    __shared__ float gq[K];
    int b = blockIdx.x, tid = threadIdx.x;
    const float* mb = g_means + b * K * C;
    const float* yb = g_Y + b * K * C;

    for (int i = tid; i < K * C; i += 256) msm[i >> 7][i & 127] = mb[i];
    __syncthreads();

    if (tid < K) {
        float a = 0.f;
#pragma unroll 8
        for (int d = 0; d < C; d++) a += yb[tid * C + d] * msm[tid][d];
        gq[tid] = a;
    }
    __syncthreads();

    for (int i = tid; i < K * K; i += 256) {
        int p = i >> 6, q = i & 63;
        float dot = 0.f;
#pragma unroll 8
        for (int d = 0; d < C; d++) dot += yb[p * C + d] * msm[q][d];
        float quad = gq[p] + gq[q] - 2.f * dot;
        g_adj[b * K * K + i] = (p == q) ? 0.f : expf(-quad) * adj_mask[i];
    }
    __syncthreads();

    for (int i = tid; i < K * C; i += 256) {
        int p = i >> 7, d = i & 127;
        const float* arow = g_adj + b * K * K + p * K;
        float acc = 0.f;
#pragma unroll 8
        for (int q = 0; q < K; q++) acc += arow[q] * msm[q][d];
        g_adjm[b * K * C + i] = acc;
    }
}

// ---------------- kernel 7: BN statistics (analytic) ----------------
// 1 block, 128 threads (thread = channel d)
__global__ void k_bnstats(const float* __restrict__ gamma, const float* __restrict__ beta) {
    int d = threadIdx.x;
    float S1 = 0.f, S2 = 0.f;
    for (int bk = 0; bk < B * K; bk++) {
        float cnt = g_cnt[bk];
        float denom = (cnt == 0.f) ? 1.f : cnt;
        float m = g_means[bk * C + d];
        float am = g_adjm[bk * C + d];
        float sxw = m * denom;                  // true segment sum of xw
        S1 += sxw + cnt * am;
        S2 += 2.f * am * sxw + cnt * am * am;
    }
    S2 += g_sumsq[d];
    float mu = S1 / NTOT;
    float var = S2 / NTOT - mu * mu;
    float s = gamma[d] * rsqrtf(var + BN_EPS);
    g_s[d] = s;
    g_t[d] = beta[d] - mu * s;
}

// ---------------- kernel 8: bias table bias[b][d][k] = s[d]*adjm[b][k][d] + t[d] ----------------
__global__ void k_bias() {
    int b = blockIdx.x;
    for (int i = threadIdx.x; i < C * K; i += 256) {
        int d = i >> 6, k = i & 63;
        g_bias[b * C * K + i] = g_s[d] * g_adjm[(b * K + k) * C + d] + g_t[d];
    }
}

// ---------------- kernel 9: out = s[d]*xw + bias[b][d][idx[p]] ----------------
// grid: B*32 blocks (2048-pixel chunks), 256 threads
__global__ __launch_bounds__(256) void k_out(const int* __restrict__ idx,
                                             float* __restrict__ out) {
    __shared__ float bsm[C][K];   // [d][k]
    __shared__ float ssm[C];
    int b = blockIdx.x >> 5;
    int p0 = (blockIdx.x & 31) << 11;
    int tid = threadIdx.x;

    for (int i = tid; i < C * K; i += 256) ((float*)bsm)[i] = g_bias[b * C * K + i];
    if (tid < C) ssm[tid] = g_s[tid];
    __syncthreads();

    int kr[8];
    {
        const int4* ip = (const int4*)(idx + b * HW + p0 + tid * 8);
        int4 i0 = ip[0], i1 = ip[1];
        kr[0] = i0.x; kr[1] = i0.y; kr[2] = i0.z; kr[3] = i0.w;
        kr[4] = i1.x; kr[5] = i1.y; kr[6] = i1.z; kr[7] = i1.w;
    }

    const float* xwb = g_xw + (size_t)b * C * HW;
    float* ob = out + (size_t)b * C * HW;

    for (int d = 0; d < C; d++) {
        float s = ssm[d];
        const float* bd = bsm[d];
        const float4* xr = (const float4*)(xwb + (size_t)d * HW + p0 + tid * 8);
        float4* orow = (float4*)(ob + (size_t)d * HW + p0 + tid * 8);
        float4 v0 = xr[0], v1 = xr[1];
        float4 r0, r1;
        r0.x = fmaf(s, v0.x, bd[kr[0]]);
        r0.y = fmaf(s, v0.y, bd[kr[1]]);
        r0.z = fmaf(s, v0.z, bd[kr[2]]);
        r0.w = fmaf(s, v0.w, bd[kr[3]]);
        r1.x = fmaf(s, v1.x, bd[kr[4]]);
        r1.y = fmaf(s, v1.y, bd[kr[5]]);
        r1.z = fmaf(s, v1.z, bd[kr[6]]);
        r1.w = fmaf(s, v1.w, bd[kr[7]]);
        orow[0] = r0;
        orow[1] = r1;
    }
}

// ---------------- launch ----------------
extern "C" void kernel_launch(void* const* d_in, const int* in_sizes, int n_in,
                              void* d_out, int out_size) {
    const float* x        = (const float*)d_in[0];
    const int*   index    = (const int*)d_in[1];
    const float* weight   = (const float*)d_in[2];
    const float* Wm       = (const float*)d_in[3];
    const float* adj_mask = (const float*)d_in[4];
    const float* gamma    = (const float*)d_in[5];
    const float* beta     = (const float*)d_in[6];
    float* out = (float*)d_out;

    k_zero<<<256, 256>>>();
    k_segsum<<<B * 32, 256>>>(x, index);
    k_gemm<<<4096, 256>>>(x, weight);
    k_means<<<B * K, 128>>>(weight);
    k_M<<<128, 128>>>(Wm);
    k_Y<<<B * K, 128>>>();
    k_adj<<<B, 256>>>(adj_mask);
    k_bnstats<<<1, 128>>>(gamma, beta);
    k_bias<<<B, 256>>>();
    k_out<<<B * 32, 256>>>(index, out);
}

// round 5
// speedup vs baseline: 1.0178x; 1.0178x over previous
#include <cuda_runtime.h>
#include <cuda_bf16.h>
#include <cstdint>

#define B 8
#define C 128
#define HW 65536
#define K 64
#define NTOT 524288.0f
#define BN_EPS 1e-5f

// ---------------- scratch (device globals; no allocation allowed) ----------------
__device__ float g_xw[(size_t)B * C * HW];      // 268 MB scratch for xw
__device__ float g_sums_x[B * K * C];           // segment sums of x
__device__ float g_cnt[B * K];                  // segment counts
__device__ float g_sumsq[C];                    // per-channel sum of xw^2
__device__ float g_means[B * K * C];
__device__ float g_M[C * C];                    // W @ W^T
__device__ float g_Y[B * K * C];                // means @ M
__device__ float g_adj[B * K * K];
__device__ float g_adjm[B * K * C];             // adj_nd @ means
__device__ float g_bias[B * C * K];             // [b][d][k] = s*adjm + t
__device__ float g_s[C];
__device__ float g_t[C];

// ---------------- kernel 0: zero accumulators ----------------
__global__ void k_zero() {
    int i = blockIdx.x * blockDim.x + threadIdx.x;
    if (i < B * K * C) g_sums_x[i] = 0.f;
    if (i < B * K)     g_cnt[i] = 0.f;
    if (i < C)         g_sumsq[i] = 0.f;
}

// ---------------- kernel 1: segment sums of x + counts ----------------
__global__ __launch_bounds__(256) void k_segsum(const float* __restrict__ x,
                                                const int* __restrict__ idx) {
    __shared__ float ssum[C][K];
    __shared__ int   sidx[2048];
    __shared__ float scnt[K];
    int b = blockIdx.x >> 5;
    int p0 = (blockIdx.x & 31) << 11;
    int tid = threadIdx.x;

    for (int i = tid; i < C * K; i += 256) ((float*)ssum)[i] = 0.f;
    if (tid < K) scnt[tid] = 0.f;
    __syncthreads();

    for (int i = tid; i < 2048; i += 256) {
        int k = idx[b * HW + p0 + i];
        sidx[i] = k;
        atomicAdd(&scnt[k], 1.f);
    }
    __syncthreads();

    const float* xb = x + (size_t)b * C * HW + p0;
    for (int c = 0; c < C; c++) {
        const float* xc = xb + (size_t)c * HW;
        for (int i = tid; i < 2048; i += 256) {
            atomicAdd(&ssum[c][sidx[i]], xc[i]);
        }
    }
    __syncthreads();

    for (int i = tid; i < C * K; i += 256) {
        int c = i >> 6, k = i & 63;
        atomicAdd(&g_sums_x[(b * K + k) * C + c], ssum[c][k]);
    }
    if (tid < K) atomicAdd(&g_cnt[b * K + tid], scnt[tid]);
}

// ================= kernel 2: mma.sync bf16 GEMM xw = x @ weight (+ sum xw^2) =================
// Per block: tile M=128 (channels d) x N=128 (pixels p), K=128 (channels in).
// Split-bf16: xw ~= wh*xh + wh*xl + wl*xh, fp32 accumulate (~1e-5 rel err).
// A = weight^T [d][c] bf16 hi/lo in smem; B = x^T [p][c] bf16 hi/lo in smem.
// mma.sync.aligned.m16n8k16.row.col.f32.bf16.bf16.f32 (compute_103-baseline legal).
#define PITCH 132           // bf16 elems per smem row (264 B)
#define GSM_AH 0
#define GSM_AL 33792
#define GSM_BH 67584
#define GSM_BL 101376
#define GSM_STAGE 135168    // fp32 [64][132] = 33792 B
#define GSM_TOTAL 168960

#define MMA_BF16(d, a, bb) \
    asm volatile("mma.sync.aligned.m16n8k16.row.col.f32.bf16.bf16.f32 " \
        "{%0,%1,%2,%3}, {%4,%5,%6,%7}, {%8,%9}, {%0,%1,%2,%3};" \
        : "+f"((d)[0]), "+f"((d)[1]), "+f"((d)[2]), "+f"((d)[3]) \
        : "r"((a)[0]), "r"((a)[1]), "r"((a)[2]), "r"((a)[3]), \
          "r"((bb)[0]), "r"((bb)[1]))

__global__ __launch_bounds__(256, 1) void k_gemm_mma(const float* __restrict__ x,
                                                     const float* __restrict__ w) {
    extern __shared__ char smem[];
    __nv_bfloat16* Ah = (__nv_bfloat16*)(smem + GSM_AH);
    __nv_bfloat16* Al = (__nv_bfloat16*)(smem + GSM_AL);
    __nv_bfloat16* Bh = (__nv_bfloat16*)(smem + GSM_BH);
    __nv_bfloat16* Bl = (__nv_bfloat16*)(smem + GSM_BL);
    float* stage  = (float*)(smem + GSM_STAGE);
    float* estage = (float*)smem;            // epilogue alias over Ah+Al (67584 B)
    __shared__ float sq[C];

    int tid = threadIdx.x;
    int b = blockIdx.x >> 9;
    int p0 = (blockIdx.x & 511) << 7;
    const float* xb = x + (size_t)b * C * HW + p0;

    if (tid < C) sq[tid] = 0.f;

    // ---- 4 rounds: r=0,1 transpose weight -> A(hi,lo); r=2,3 transpose x -> B(hi,lo) ----
    for (int r = 0; r < 4; r++) {
        __syncthreads();
        for (int e = tid; e < 2048; e += 256) {
            int row = e >> 5, c4 = (e & 31) * 4;
            float4 v;
            if (r < 2) v = *(const float4*)(w  + (size_t)(r * 64 + row) * C  + c4);
            else       v = *(const float4*)(xb + (size_t)((r - 2) * 64 + row) * HW + c4);
            *(float4*)&stage[row * PITCH + c4] = v;
        }
        __syncthreads();
        int orow = tid & 127;
        int half = tid >> 7;
        __nv_bfloat16* Dh = (r < 2) ? Ah : Bh;
        __nv_bfloat16* Dl = (r < 2) ? Al : Bl;
        int colbase = (r & 1) * 64 + half * 32;
#pragma unroll 8
        for (int j = 0; j < 32; j += 2) {
            int cl = half * 32 + j;
            float v0 = stage[cl * PITCH + orow];
            float v1 = stage[(cl + 1) * PITCH + orow];
            __nv_bfloat16 h0 = __float2bfloat16(v0);
            __nv_bfloat16 h1 = __float2bfloat16(v1);
            float l0 = v0 - __bfloat162float(h0);
            float l1 = v1 - __bfloat162float(h1);
            __nv_bfloat162 hp; hp.x = h0; hp.y = h1;
            __nv_bfloat162 lp; lp.x = __float2bfloat16(l0); lp.y = __float2bfloat16(l1);
            *(__nv_bfloat162*)&Dh[orow * PITCH + colbase + j] = hp;
            *(__nv_bfloat162*)&Dl[orow * PITCH + colbase + j] = lp;
        }
    }
    __syncthreads();

    // ---- mainloop ----
    int lane = tid & 31, wid = tid >> 5;
    int gid = lane >> 2, tig = lane & 3;
    int dbase = (wid & 3) * 32;        // warp m-tile
    int pbase = (wid >> 2) * 64;       // warp n-tile

    float D[2][8][4];
#pragma unroll
    for (int mf = 0; mf < 2; mf++)
#pragma unroll
        for (int nf = 0; nf < 8; nf++)
#pragma unroll
            for (int q = 0; q < 4; q++) D[mf][nf][q] = 0.f;

#pragma unroll
    for (int ks = 0; ks < 8; ks++) {
        int k0 = ks * 16;
        uint32_t ah[2][4], al[2][4];
#pragma unroll
        for (int mf = 0; mf < 2; mf++) {
            int r0 = dbase + mf * 16 + gid;
            ah[mf][0] = *(const uint32_t*)&Ah[r0 * PITCH + k0 + 2 * tig];
            ah[mf][1] = *(const uint32_t*)&Ah[(r0 + 8) * PITCH + k0 + 2 * tig];
            ah[mf][2] = *(const uint32_t*)&Ah[r0 * PITCH + k0 + 8 + 2 * tig];
            ah[mf][3] = *(const uint32_t*)&Ah[(r0 + 8) * PITCH + k0 + 8 + 2 * tig];
            al[mf][0] = *(const uint32_t*)&Al[r0 * PITCH + k0 + 2 * tig];
            al[mf][1] = *(const uint32_t*)&Al[(r0 + 8) * PITCH + k0 + 2 * tig];
            al[mf][2] = *(const uint32_t*)&Al[r0 * PITCH + k0 + 8 + 2 * tig];
            al[mf][3] = *(const uint32_t*)&Al[(r0 + 8) * PITCH + k0 + 8 + 2 * tig];
        }
        uint32_t bh[8][2], bl[8][2];
#pragma unroll
        for (int nf = 0; nf < 8; nf++) {
            int cn = pbase + nf * 8 + gid;
            bh[nf][0] = *(const uint32_t*)&Bh[cn * PITCH + k0 + 2 * tig];
            bh[nf][1] = *(const uint32_t*)&Bh[cn * PITCH + k0 + 8 + 2 * tig];
            bl[nf][0] = *(const uint32_t*)&Bl[cn * PITCH + k0 + 2 * tig];
            bl[nf][1] = *(const uint32_t*)&Bl[cn * PITCH + k0 + 8 + 2 * tig];
        }
#pragma unroll
        for (int mf = 0; mf < 2; mf++)
#pragma unroll
            for (int nf = 0; nf < 8; nf++) {
                MMA_BF16(D[mf][nf], ah[mf], bh[nf]);
                MMA_BF16(D[mf][nf], ah[mf], bl[nf]);
                MMA_BF16(D[mf][nf], al[mf], bh[nf]);
            }
    }
    __syncthreads();   // all A/B smem reads done; estage may alias

    // ---- epilogue: ssq from regs, restage D, coalesced store ----
    float ss[2][2] = {{0.f, 0.f}, {0.f, 0.f}};
#pragma unroll
    for (int mf = 0; mf < 2; mf++) {
#pragma unroll
        for (int nf = 0; nf < 8; nf++) {
            float* dd = D[mf][nf];
            ss[mf][0] += dd[0] * dd[0] + dd[1] * dd[1];
            ss[mf][1] += dd[2] * dd[2] + dd[3] * dd[3];
            int r0 = dbase + mf * 16 + gid;
            int cn = pbase + nf * 8 + 2 * tig;
            float2 v01; v01.x = dd[0]; v01.y = dd[1];
            float2 v23; v23.x = dd[2]; v23.y = dd[3];
            *(float2*)&estage[r0 * PITCH + cn] = v01;
            *(float2*)&estage[(r0 + 8) * PITCH + cn] = v23;
        }
        atomicAdd(&sq[dbase + mf * 16 + gid], ss[mf][0]);
        atomicAdd(&sq[dbase + mf * 16 + 8 + gid], ss[mf][1]);
    }
    __syncthreads();

    float* xwb = g_xw + (size_t)b * C * HW + p0;
#pragma unroll
    for (int i = 0; i < 16; i++) {
        int flat = i * 256 + tid;          // 4096 float4 total
        int row = flat >> 5, c4 = (flat & 31) * 4;
        float4 v = *(float4*)&estage[row * PITCH + c4];
        *(float4*)(xwb + (size_t)row * HW + c4) = v;
    }
    if (tid < C) atomicAdd(&g_sumsq[tid], sq[tid]);
}

// ---------------- kernel 3: means[b,k,d] = (sums_x[b,k,:] @ weight) / denom ----------------
__global__ void k_means(const float* __restrict__ w) {
    __shared__ float s[C];
    int bk = blockIdx.x;
    int d = threadIdx.x;
    s[d] = g_sums_x[bk * C + d];
    __syncthreads();
    float cnt = g_cnt[bk];
    float denom = (cnt == 0.f) ? 1.f : cnt;
    float acc = 0.f;
#pragma unroll 8
    for (int c = 0; c < C; c++) acc += s[c] * w[c * C + d];
    g_means[bk * C + d] = acc / denom;
}

// ---------------- kernel 4: M = W @ W^T ----------------
__global__ void k_M(const float* __restrict__ Wm) {
    __shared__ float wi[C];
    int i = blockIdx.x, j = threadIdx.x;
    wi[j] = Wm[i * C + j];
    __syncthreads();
    float acc = 0.f;
#pragma unroll 8
    for (int c = 0; c < C; c++) acc += wi[c] * Wm[j * C + c];
    g_M[i * C + j] = acc;
}

// ---------------- kernel 5: Y[b,k,d] = means[b,k,:] @ M ----------------
__global__ void k_Y() {
    __shared__ float ms[C];
    int bk = blockIdx.x;
    int d = threadIdx.x;
    ms[d] = g_means[bk * C + d];
    __syncthreads();
    float acc = 0.f;
#pragma unroll 8
    for (int c = 0; c < C; c++) acc += ms[c] * g_M[c * C + d];
    g_Y[bk * C + d] = acc;
}

// ---------------- kernel 6: adjacency + adj_means ----------------
__global__ __launch_bounds__(256) void k_adj(const float* __restrict__ adj_mask) {
    __shared__ float msm[K][C + 1];
    __shared__ float gq[K];
    int b = blockIdx.x, tid = threadIdx.x;
    const float* mb = g_means + b * K * C;
    const float* yb = g_Y + b * K * C;

    for (int i = tid; i < K * C; i += 256) msm[i >> 7][i & 127] = mb[i];
    __syncthreads();

    if (tid < K) {
        float a = 0.f;
#pragma unroll 8
        for (int d = 0; d < C; d++) a += yb[tid * C + d] * msm[tid][d];
        gq[tid] = a;
    }
    __syncthreads();

    for (int i = tid; i < K * K; i += 256) {
        int p = i >> 6, q = i & 63;
        float dot = 0.f;
#pragma unroll 8
        for (int d = 0; d < C; d++) dot += yb[p * C + d] * msm[q][d];
        float quad = gq[p] + gq[q] - 2.f * dot;
        g_adj[b * K * K + i] = (p == q) ? 0.f : expf(-quad) * adj_mask[i];
    }
    __syncthreads();

    for (int i = tid; i < K * C; i += 256) {
        int p = i >> 7, d = i & 127;
        const float* arow = g_adj + b * K * K + p * K;
        float acc = 0.f;
#pragma unroll 8
        for (int q = 0; q < K; q++) acc += arow[q] * msm[q][d];
        g_adjm[b * K * C + i] = acc;
    }
}

// ---------------- kernel 7: BN statistics (analytic) ----------------
__global__ void k_bnstats(const float* __restrict__ gamma, const float* __restrict__ beta) {
    int d = threadIdx.x;
    float S1 = 0.f, S2 = 0.f;
    for (int bk = 0; bk < B * K; bk++) {
        float cnt = g_cnt[bk];
        float denom = (cnt == 0.f) ? 1.f : cnt;
        float m = g_means[bk * C + d];
        float am = g_adjm[bk * C + d];
        float sxw = m * denom;
        S1 += sxw + cnt * am;
        S2 += 2.f * am * sxw + cnt * am * am;
    }
    S2 += g_sumsq[d];
    float mu = S1 / NTOT;
    float var = S2 / NTOT - mu * mu;
    float s = gamma[d] * rsqrtf(var + BN_EPS);
    g_s[d] = s;
    g_t[d] = beta[d] - mu * s;
}

// ---------------- kernel 8: bias table ----------------
__global__ void k_bias() {
    int b = blockIdx.x;
    for (int i = threadIdx.x; i < C * K; i += 256) {
        int d = i >> 6, k = i & 63;
        g_bias[b * C * K + i] = g_s[d] * g_adjm[(b * K + k) * C + d] + g_t[d];
    }
}

// ---------------- kernel 9: out = s[d]*xw + bias[b][d][idx[p]] ----------------
__global__ __launch_bounds__(256) void k_out(const int* __restrict__ idx,
                                             float* __restrict__ out) {
    __shared__ float bsm[C][K];
    __shared__ float ssm[C];
    int b = blockIdx.x >> 5;
    int p0 = (blockIdx.x & 31) << 11;
    int tid = threadIdx.x;

    for (int i = tid; i < C * K; i += 256) ((float*)bsm)[i] = g_bias[b * C * K + i];
    if (tid < C) ssm[tid] = g_s[tid];
    __syncthreads();

    int kr[8];
    {
        const int4* ip = (const int4*)(idx + b * HW + p0 + tid * 8);
        int4 i0 = ip[0], i1 = ip[1];
        kr[0] = i0.x; kr[1] = i0.y; kr[2] = i0.z; kr[3] = i0.w;
        kr[4] = i1.x; kr[5] = i1.y; kr[6] = i1.z; kr[7] = i1.w;
    }

    const float* xwb = g_xw + (size_t)b * C * HW;
    float* ob = out + (size_t)b * C * HW;

    for (int d = 0; d < C; d++) {
        float s = ssm[d];
        const float* bd = bsm[d];
        const float4* xr = (const float4*)(xwb + (size_t)d * HW + p0 + tid * 8);
        float4* orow = (float4*)(ob + (size_t)d * HW + p0 + tid * 8);
        float4 v0 = xr[0], v1 = xr[1];
        float4 r0, r1;
        r0.x = fmaf(s, v0.x, bd[kr[0]]);
        r0.y = fmaf(s, v0.y, bd[kr[1]]);
        r0.z = fmaf(s, v0.z, bd[kr[2]]);
        r0.w = fmaf(s, v0.w, bd[kr[3]]);
        r1.x = fmaf(s, v1.x, bd[kr[4]]);
        r1.y = fmaf(s, v1.y, bd[kr[5]]);
        r1.z = fmaf(s, v1.z, bd[kr[6]]);
        r1.w = fmaf(s, v1.w, bd[kr[7]]);
        orow[0] = r0;
        orow[1] = r1;
    }
}

// ---------------- launch ----------------
extern "C" void kernel_launch(void* const* d_in, const int* in_sizes, int n_in,
                              void* d_out, int out_size) {
    const float* x        = (const float*)d_in[0];
    const int*   index    = (const int*)d_in[1];
    const float* weight   = (const float*)d_in[2];
    const float* Wm       = (const float*)d_in[3];
    const float* adj_mask = (const float*)d_in[4];
    const float* gamma    = (const float*)d_in[5];
    const float* beta     = (const float*)d_in[6];
    float* out = (float*)d_out;

    cudaFuncSetAttribute(k_gemm_mma, cudaFuncAttributeMaxDynamicSharedMemorySize, GSM_TOTAL);

    k_zero<<<256, 256>>>();
    k_segsum<<<B * 32, 256>>>(x, index);
    k_gemm_mma<<<4096, 256, GSM_TOTAL>>>(x, weight);
    k_means<<<B * K, 128>>>(weight);
    k_M<<<128, 128>>>(Wm);
    k_Y<<<B * K, 128>>>();
    k_adj<<<B, 256>>>(adj_mask);
    k_bnstats<<<1, 128>>>(gamma, beta);
    k_bias<<<B, 256>>>();
    k_out<<<B * 32, 256>>>(index, out);
}

// round 8
// speedup vs baseline: 1.5405x; 1.5136x over previous
#include <cuda_runtime.h>
#include <cuda_bf16.h>
#include <cstdint>

#define B 8
#define C 128
#define HW 65536
#define K 64
#define NTOT 524288.0f
#define BN_EPS 1e-5f

// ---------------- scratch (device globals; no allocation allowed) ----------------
__device__ float g_G[C * C];                    // Gram matrix sum_p x x^T
__device__ float g_sums_x[B * K * C];           // segment sums of x
__device__ float g_cnt[B * K];                  // segment counts
__device__ float g_sumsq[C];                    // per-channel sum of xw^2
__device__ float g_means[B * K * C];
__device__ float g_M[C * C];                    // W @ W^T
__device__ float g_Y[B * K * C];                // means @ M
__device__ float g_adj[B * K * K];
__device__ float g_adjm[B * K * C];             // adj_nd @ means
__device__ float g_bias[B * C * K];             // [b][d][k] = s*adjm + t
__device__ float g_s[C];
__device__ float g_t[C];

#define MMA_BF16(d, a, bb) \
    asm volatile("mma.sync.aligned.m16n8k16.row.col.f32.bf16.bf16.f32 " \
        "{%0,%1,%2,%3}, {%4,%5,%6,%7}, {%8,%9}, {%0,%1,%2,%3};" \
        : "+f"((d)[0]), "+f"((d)[1]), "+f"((d)[2]), "+f"((d)[3]) \
        : "r"((a)[0]), "r"((a)[1]), "r"((a)[2]), "r"((a)[3]), \
          "r"((bb)[0]), "r"((bb)[1]))

// ---------------- kernel 0: zero accumulators ----------------
__global__ void k_zero() {
    int i = blockIdx.x * blockDim.x + threadIdx.x;
    if (i < B * K * C) g_sums_x[i] = 0.f;
    if (i < C * C)     g_G[i] = 0.f;
    if (i < B * K)     g_cnt[i] = 0.f;
}

// ================= kernel 1: fused stats pass (G, segment sums, counts) =================
// grid 256 (8 b x 32 segs of 2048 pixels), 256 threads, 16 chunks of 128 pixels.
// Per chunk: x tile [128c][128p] -> bf16 hi/lo smem (layout matches mma directly),
// one-hot [64k][128p]; HMMA: G += Xh·Xh^T (contraction p), S += OH·(Xh+Xl)^T.
#define P1_PITCH 132
#define P1_XH 0
#define P1_XL 33792
#define P1_OH 67584
#define P1_TOTAL 84480

__global__ __launch_bounds__(256, 1) void k_pass1(const float* __restrict__ x,
                                                  const int* __restrict__ idx) {
    extern __shared__ char smem[];
    __nv_bfloat16* Xh = (__nv_bfloat16*)(smem + P1_XH);
    __nv_bfloat16* Xl = (__nv_bfloat16*)(smem + P1_XL);
    __nv_bfloat16* OH = (__nv_bfloat16*)(smem + P1_OH);
    __shared__ int   sidx[128];
    __shared__ float hcnt[K];

    int tid = threadIdx.x;
    int b   = blockIdx.x >> 5;
    int seg = blockIdx.x & 31;
    int lane = tid & 31, wid = tid >> 5;
    int gid = lane >> 2, tig = lane & 3;
    int dbase  = (wid & 3) * 32;    // G m-tile (rows c1)
    int msbase = (wid & 3) * 16;    // S m-tile (rows k)
    int pbase  = (wid >> 2) * 64;   // n-half (cols c2 / c)

    if (tid < K) hcnt[tid] = 0.f;

    float Dg[2][8][4];
    float Ds[8][4];
#pragma unroll
    for (int mf = 0; mf < 2; mf++)
#pragma unroll
        for (int nf = 0; nf < 8; nf++)
#pragma unroll
            for (int q = 0; q < 4; q++) Dg[mf][nf][q] = 0.f;
#pragma unroll
    for (int nf = 0; nf < 8; nf++)
#pragma unroll
        for (int q = 0; q < 4; q++) Ds[nf][q] = 0.f;

    const float* xb = x + (size_t)b * C * HW + seg * 2048;
    const int*   ib = idx + b * HW + seg * 2048;

    for (int ch = 0; ch < 16; ch++) {
        __syncthreads();
        if (tid < 128) sidx[tid] = ib[ch * 128 + tid];
        for (int i = tid; i < 4224; i += 256) ((uint32_t*)OH)[i] = 0u;
        for (int e = tid; e < 4096; e += 256) {
            int row = e >> 5, p4 = (e & 31) * 4;
            float4 v = *(const float4*)(xb + (size_t)row * HW + ch * 128 + p4);
            __nv_bfloat162 h0 = __floats2bfloat162_rn(v.x, v.y);
            __nv_bfloat162 h1 = __floats2bfloat162_rn(v.z, v.w);
            float l0 = v.x - __bfloat162float(h0.x);
            float l1 = v.y - __bfloat162float(h0.y);
            float l2 = v.z - __bfloat162float(h1.x);
            float l3 = v.w - __bfloat162float(h1.y);
            __nv_bfloat162 g0 = __floats2bfloat162_rn(l0, l1);
            __nv_bfloat162 g1 = __floats2bfloat162_rn(l2, l3);
            *(__nv_bfloat162*)&Xh[row * P1_PITCH + p4]     = h0;
            *(__nv_bfloat162*)&Xh[row * P1_PITCH + p4 + 2] = h1;
            *(__nv_bfloat162*)&Xl[row * P1_PITCH + p4]     = g0;
            *(__nv_bfloat162*)&Xl[row * P1_PITCH + p4 + 2] = g1;
        }
        __syncthreads();
        if (tid < 128) {
            int k = sidx[tid];
            OH[k * P1_PITCH + tid] = __float2bfloat16(1.0f);
            atomicAdd(&hcnt[k], 1.f);
        }
        __syncthreads();

#pragma unroll
        for (int ks = 0; ks < 8; ks++) {
            int k0 = ks * 16;
            uint32_t bh[8][2], bl[8][2];
#pragma unroll
            for (int nf = 0; nf < 8; nf++) {
                int cn = pbase + nf * 8 + gid;
                bh[nf][0] = *(const uint32_t*)&Xh[cn * P1_PITCH + k0 + 2 * tig];
                bh[nf][1] = *(const uint32_t*)&Xh[cn * P1_PITCH + k0 + 8 + 2 * tig];
                bl[nf][0] = *(const uint32_t*)&Xl[cn * P1_PITCH + k0 + 2 * tig];
                bl[nf][1] = *(const uint32_t*)&Xl[cn * P1_PITCH + k0 + 8 + 2 * tig];
            }
            uint32_t ah[2][4];
#pragma unroll
            for (int mf = 0; mf < 2; mf++) {
                int r0 = dbase + mf * 16 + gid;
                ah[mf][0] = *(const uint32_t*)&Xh[r0 * P1_PITCH + k0 + 2 * tig];
                ah[mf][1] = *(const uint32_t*)&Xh[(r0 + 8) * P1_PITCH + k0 + 2 * tig];
                ah[mf][2] = *(const uint32_t*)&Xh[r0 * P1_PITCH + k0 + 8 + 2 * tig];
                ah[mf][3] = *(const uint32_t*)&Xh[(r0 + 8) * P1_PITCH + k0 + 8 + 2 * tig];
            }
            uint32_t ao[4];
            {
                int m0 = msbase + gid;
                ao[0] = *(const uint32_t*)&OH[m0 * P1_PITCH + k0 + 2 * tig];
                ao[1] = *(const uint32_t*)&OH[(m0 + 8) * P1_PITCH + k0 + 2 * tig];
                ao[2] = *(const uint32_t*)&OH[m0 * P1_PITCH + k0 + 8 + 2 * tig];
                ao[3] = *(const uint32_t*)&OH[(m0 + 8) * P1_PITCH + k0 + 8 + 2 * tig];
            }
#pragma unroll
            for (int mf = 0; mf < 2; mf++)
#pragma unroll
                for (int nf = 0; nf < 8; nf++)
                    MMA_BF16(Dg[mf][nf], ah[mf], bh[nf]);
#pragma unroll
            for (int nf = 0; nf < 8; nf++) {
                MMA_BF16(Ds[nf], ao, bh[nf]);
                MMA_BF16(Ds[nf], ao, bl[nf]);
            }
        }
    }

    // ---- flush partials ----
#pragma unroll
    for (int mf = 0; mf < 2; mf++)
#pragma unroll
        for (int nf = 0; nf < 8; nf++) {
            int r0 = dbase + mf * 16 + gid;
            int cn = pbase + nf * 8 + 2 * tig;
            atomicAdd(&g_G[r0 * C + cn],           Dg[mf][nf][0]);
            atomicAdd(&g_G[r0 * C + cn + 1],       Dg[mf][nf][1]);
            atomicAdd(&g_G[(r0 + 8) * C + cn],     Dg[mf][nf][2]);
            atomicAdd(&g_G[(r0 + 8) * C + cn + 1], Dg[mf][nf][3]);
        }
#pragma unroll
    for (int nf = 0; nf < 8; nf++) {
        int m0 = msbase + gid;
        int cn = pbase + nf * 8 + 2 * tig;
        atomicAdd(&g_sums_x[(b * K + m0) * C + cn],           Ds[nf][0]);
        atomicAdd(&g_sums_x[(b * K + m0) * C + cn + 1],       Ds[nf][1]);
        atomicAdd(&g_sums_x[(b * K + m0 + 8) * C + cn],       Ds[nf][2]);
        atomicAdd(&g_sums_x[(b * K + m0 + 8) * C + cn + 1],   Ds[nf][3]);
    }
    __syncthreads();
    if (tid < K) atomicAdd(&g_cnt[b * K + tid], hcnt[tid]);
}

// ---------------- kernel 3: means[b,k,d] = (sums_x[b,k,:] @ weight) / denom ----------------
__global__ void k_means(const float* __restrict__ w) {
    __shared__ float s[C];
    int bk = blockIdx.x;
    int d = threadIdx.x;
    s[d] = g_sums_x[bk * C + d];
    __syncthreads();
    float cnt = g_cnt[bk];
    float denom = (cnt == 0.f) ? 1.f : cnt;
    float acc = 0.f;
#pragma unroll 8
    for (int c = 0; c < C; c++) acc += s[c] * w[c * C + d];
    g_means[bk * C + d] = acc / denom;
}

// ---------------- kernel 4: M = W @ W^T ----------------
__global__ void k_M(const float* __restrict__ Wm) {
    __shared__ float wi[C];
    int i = blockIdx.x, j = threadIdx.x;
    wi[j] = Wm[i * C + j];
    __syncthreads();
    float acc = 0.f;
#pragma unroll 8
    for (int c = 0; c < C; c++) acc += wi[c] * Wm[j * C + c];
    g_M[i * C + j] = acc;
}

// ---------------- kernel 5: Y[b,k,d] = means[b,k,:] @ M ----------------
__global__ void k_Y() {
    __shared__ float ms[C];
    int bk = blockIdx.x;
    int d = threadIdx.x;
    ms[d] = g_means[bk * C + d];
    __syncthreads();
    float acc = 0.f;
#pragma unroll 8
    for (int c = 0; c < C; c++) acc += ms[c] * g_M[c * C + d];
    g_Y[bk * C + d] = acc;
}

// ---------------- kernel 6: adjacency + adj_means ----------------
__global__ __launch_bounds__(256) void k_adj(const float* __restrict__ adj_mask) {
    __shared__ float msm[K][C + 1];
    __shared__ float gq[K];
    int b = blockIdx.x, tid = threadIdx.x;
    const float* mb = g_means + b * K * C;
    const float* yb = g_Y + b * K * C;

    for (int i = tid; i < K * C; i += 256) msm[i >> 7][i & 127] = mb[i];
    __syncthreads();

    if (tid < K) {
        float a = 0.f;
#pragma unroll 8
        for (int d = 0; d < C; d++) a += yb[tid * C + d] * msm[tid][d];
        gq[tid] = a;
    }
    __syncthreads();

    for (int i = tid; i < K * K; i += 256) {
        int p = i >> 6, q = i & 63;
        float dot = 0.f;
#pragma unroll 8
        for (int d = 0; d < C; d++) dot += yb[p * C + d] * msm[q][d];
        float quad = gq[p] + gq[q] - 2.f * dot;
        g_adj[b * K * K + i] = (p == q) ? 0.f : expf(-quad) * adj_mask[i];
    }
    __syncthreads();

    for (int i = tid; i < K * C; i += 256) {
        int p = i >> 7, d = i & 127;
        const float* arow = g_adj + b * K * K + p * K;
        float acc = 0.f;
#pragma unroll 8
        for (int q = 0; q < K; q++) acc += arow[q] * msm[q][d];
        g_adjm[b * K * C + i] = acc;
    }
}

// ---------------- kernel 6.5: sumsq[d] = w_d^T G w_d ----------------
__global__ void k_sumsq(const float* __restrict__ w) {
    __shared__ float wcol[C];
    __shared__ float red[C];
    int d = blockIdx.x, c1 = threadIdx.x;
    wcol[c1] = w[c1 * C + d];
    __syncthreads();
    float t = 0.f;
#pragma unroll 8
    for (int c2 = 0; c2 < C; c2++) t += g_G[c1 * C + c2] * wcol[c2];
    red[c1] = t * wcol[c1];
    __syncthreads();
    for (int s = 64; s > 0; s >>= 1) {
        if (c1 < s) red[c1] += red[c1 + s];
        __syncthreads();
    }
    if (c1 == 0) g_sumsq[d] = red[0];
}

// ---------------- kernel 7: BN statistics (analytic) ----------------
__global__ void k_bnstats(const float* __restrict__ gamma, const float* __restrict__ beta) {
    int d = threadIdx.x;
    float S1 = 0.f, S2 = 0.f;
    for (int bk = 0; bk < B * K; bk++) {
        float cnt = g_cnt[bk];
        float denom = (cnt == 0.f) ? 1.f : cnt;
        float m = g_means[bk * C + d];
        float am = g_adjm[bk * C + d];
        float sxw = m * denom;
        S1 += sxw + cnt * am;
        S2 += 2.f * am * sxw + cnt * am * am;
    }
    S2 += g_sumsq[d];
    float mu = S1 / NTOT;
    float var = S2 / NTOT - mu * mu;
    float s = gamma[d] * rsqrtf(var + BN_EPS);
    g_s[d] = s;
    g_t[d] = beta[d] - mu * s;
}

// ---------------- kernel 8: bias table bias[b][d][k] = s[d]*adjm[b][k][d] + t[d] ----------------
__global__ void k_bias() {
    int b = blockIdx.x;
    for (int i = threadIdx.x; i < C * K; i += 256) {
        int d = i >> 6, k = i & 63;
        g_bias[b * C * K + i] = g_s[d] * g_adjm[(b * K + k) * C + d] + g_t[d];
    }
}

// ================= kernel 9: fused GEMM + output =================
// out[b,d,p] = s[d] * (x @ weight)[b,d,p] + bias[b,d,idx[p]]
// Same split-bf16 HMMA structure as validated R5 GEMM; epilogue applies s/bias.
#define PITCH 132
#define GSM_AH 0
#define GSM_AL 33792
#define GSM_BH 67584
#define GSM_BL 101376
#define GSM_STAGE 135168    // fp32 stage [64][132]; reused for bias table in epilogue
#define GSM_TOTAL 168960

__global__ __launch_bounds__(256, 1) void k_gemm_out(const float* __restrict__ x,
                                                     const float* __restrict__ w,
                                                     const int* __restrict__ idx,
                                                     float* __restrict__ out) {
    extern __shared__ char smem[];
    __nv_bfloat16* Ah = (__nv_bfloat16*)(smem + GSM_AH);
    __nv_bfloat16* Al = (__nv_bfloat16*)(smem + GSM_AL);
    __nv_bfloat16* Bh = (__nv_bfloat16*)(smem + GSM_BH);
    __nv_bfloat16* Bl = (__nv_bfloat16*)(smem + GSM_BL);
    float* stage  = (float*)(smem + GSM_STAGE);
    float* estage = (float*)smem;            // epilogue alias over Ah+Al (67584 B)
    __shared__ float ssm[C];
    __shared__ int   sidxp[128];

    int tid = threadIdx.x;
    int b = blockIdx.x >> 9;
    int p0 = (blockIdx.x & 511) << 7;
    const float* xb = x + (size_t)b * C * HW + p0;

    if (tid < 128) sidxp[tid] = idx[b * HW + p0 + tid];
    if (tid < C) ssm[tid] = g_s[tid];

    // ---- 4 rounds: r=0,1 transpose weight -> A(hi,lo); r=2,3 transpose x -> B(hi,lo) ----
    for (int r = 0; r < 4; r++) {
        __syncthreads();
        for (int e = tid; e < 2048; e += 256) {
            int row = e >> 5, c4 = (e & 31) * 4;
            float4 v;
            if (r < 2) v = *(const float4*)(w  + (size_t)(r * 64 + row) * C  + c4);
            else       v = *(const float4*)(xb + (size_t)((r - 2) * 64 + row) * HW + c4);
            *(float4*)&stage[row * PITCH + c4] = v;
        }
        __syncthreads();
        int orow = tid & 127;
        int half = tid >> 7;
        __nv_bfloat16* Dh = (r < 2) ? Ah : Bh;
        __nv_bfloat16* Dl = (r < 2) ? Al : Bl;
        int colbase = (r & 1) * 64 + half * 32;
#pragma unroll 8
        for (int j = 0; j < 32; j += 2) {
            int cl = half * 32 + j;
            float v0 = stage[cl * PITCH + orow];
            float v1 = stage[(cl + 1) * PITCH + orow];
            __nv_bfloat16 h0 = __float2bfloat16(v0);
            __nv_bfloat16 h1 = __float2bfloat16(v1);
            float l0 = v0 - __bfloat162float(h0);
            float l1 = v1 - __bfloat162float(h1);
            __nv_bfloat162 hp; hp.x = h0; hp.y = h1;
            __nv_bfloat162 lp; lp.x = __float2bfloat16(l0); lp.y = __float2bfloat16(l1);
            *(__nv_bfloat162*)&Dh[orow * PITCH + colbase + j] = hp;
            *(__nv_bfloat162*)&Dl[orow * PITCH + colbase + j] = lp;
        }
    }
    __syncthreads();

    // ---- mainloop ----
    int lane = tid & 31, wid = tid >> 5;
    int gid = lane >> 2, tig = lane & 3;
    int dbase = (wid & 3) * 32;        // warp m-tile
    int pbase = (wid >> 2) * 64;       // warp n-tile

    float D[2][8][4];
#pragma unroll
    for (int mf = 0; mf < 2; mf++)
#pragma unroll
        for (int nf = 0; nf < 8; nf++)
#pragma unroll
            for (int q = 0; q < 4; q++) D[mf][nf][q] = 0.f;

#pragma unroll
    for (int ks = 0; ks < 8; ks++) {
        int k0 = ks * 16;
        uint32_t ah[2][4], al[2][4];
#pragma unroll
        for (int mf = 0; mf < 2; mf++) {
            int r0 = dbase + mf * 16 + gid;
            ah[mf][0] = *(const uint32_t*)&Ah[r0 * PITCH + k0 + 2 * tig];
            ah[mf][1] = *(const uint32_t*)&Ah[(r0 + 8) * PITCH + k0 + 2 * tig];
            ah[mf][2] = *(const uint32_t*)&Ah[r0 * PITCH + k0 + 8 + 2 * tig];
            ah[mf][3] = *(const uint32_t*)&Ah[(r0 + 8) * PITCH + k0 + 8 + 2 * tig];
            al[mf][0] = *(const uint32_t*)&Al[r0 * PITCH + k0 + 2 * tig];
            al[mf][1] = *(const uint32_t*)&Al[(r0 + 8) * PITCH + k0 + 2 * tig];
            al[mf][2] = *(const uint32_t*)&Al[r0 * PITCH + k0 + 8 + 2 * tig];
            al[mf][3] = *(const uint32_t*)&Al[(r0 + 8) * PITCH + k0 + 8 + 2 * tig];
        }
        uint32_t bh[8][2], bl[8][2];
#pragma unroll
        for (int nf = 0; nf < 8; nf++) {
            int cn = pbase + nf * 8 + gid;
            bh[nf][0] = *(const uint32_t*)&Bh[cn * PITCH + k0 + 2 * tig];
            bh[nf][1] = *(const uint32_t*)&Bh[cn * PITCH + k0 + 8 + 2 * tig];
            bl[nf][0] = *(const uint32_t*)&Bl[cn * PITCH + k0 + 2 * tig];
            bl[nf][1] = *(const uint32_t*)&Bl[cn * PITCH + k0 + 8 + 2 * tig];
        }
#pragma unroll
        for (int mf = 0; mf < 2; mf++)
#pragma unroll
            for (int nf = 0; nf < 8; nf++) {
                MMA_BF16(D[mf][nf], ah[mf], bh[nf]);
                MMA_BF16(D[mf][nf], ah[mf], bl[nf]);
                MMA_BF16(D[mf][nf], al[mf], bh[nf]);
            }
    }
    __syncthreads();   // all A/B smem reads done; estage may alias

    // ---- epilogue: restage D; load bias table into stage; fused transform + store ----
#pragma unroll
    for (int mf = 0; mf < 2; mf++)
#pragma unroll
        for (int nf = 0; nf < 8; nf++) {
            float* dd = D[mf][nf];
            int r0 = dbase + mf * 16 + gid;
            int cn = pbase + nf * 8 + 2 * tig;
            float2 v01; v01.x = dd[0]; v01.y = dd[1];
            float2 v23; v23.x = dd[2]; v23.y = dd[3];
            *(float2*)&estage[r0 * PITCH + cn] = v01;
            *(float2*)&estage[(r0 + 8) * PITCH + cn] = v23;
        }
    float* bsm = stage;   // 8192 floats, fits in 33792-byte stage region
    for (int i = tid; i < C * K; i += 256) bsm[i] = g_bias[b * C * K + i];
    __syncthreads();

    float* ob = out + (size_t)b * C * HW + p0;
#pragma unroll
    for (int i = 0; i < 16; i++) {
        int flat = i * 256 + tid;          // 4096 float4 total
        int row = flat >> 5, c4 = (flat & 31) * 4;
        float4 v = *(float4*)&estage[row * PITCH + c4];
        float s = ssm[row];
        const float* brow = bsm + row * 64;
        float4 r;
        r.x = fmaf(s, v.x, brow[sidxp[c4 + 0]]);
        r.y = fmaf(s, v.y, brow[sidxp[c4 + 1]]);
        r.z = fmaf(s, v.z, brow[sidxp[c4 + 2]]);
        r.w = fmaf(s, v.w, brow[sidxp[c4 + 3]]);
        *(float4*)(ob + (size_t)row * HW + c4) = r;
    }
}

// ---------------- launch ----------------
extern "C" void kernel_launch(void* const* d_in, const int* in_sizes, int n_in,
                              void* d_out, int out_size) {
    const float* x        = (const float*)d_in[0];
    const int*   index    = (const int*)d_in[1];
    const float* weight   = (const float*)d_in[2];
    const float* Wm       = (const float*)d_in[3];
    const float* adj_mask = (const float*)d_in[4];
    const float* gamma    = (const float*)d_in[5];
    const float* beta     = (const float*)d_in[6];
    float* out = (float*)d_out;

    cudaFuncSetAttribute(k_pass1,    cudaFuncAttributeMaxDynamicSharedMemorySize, P1_TOTAL);
    cudaFuncSetAttribute(k_gemm_out, cudaFuncAttributeMaxDynamicSharedMemorySize, GSM_TOTAL);

    k_zero<<<256, 256>>>();
    k_pass1<<<256, 256, P1_TOTAL>>>(x, index);
    k_means<<<B * K, 128>>>(weight);
    k_M<<<128, 128>>>(Wm);
    k_Y<<<B * K, 128>>>();
    k_adj<<<B, 256>>>(adj_mask);
    k_sumsq<<<128, 128>>>(weight);
    k_bnstats<<<1, 128>>>(gamma, beta);
    k_bias<<<B, 256>>>();
    k_gemm_out<<<4096, 256, GSM_TOTAL>>>(x, weight, index, out);
}